// round 1
// baseline (speedup 1.0000x reference)
#include <cuda_runtime.h>
#include <math_constants.h>

// Shapes
#define IN_DIM   256
#define CODE_LEN 128
#define MEM_LEN  65536
// Output layout (all float32, flattened tuple):
//   [0]                      loss
//   [1 .. 1+MEM_LEN*128)     new_memory
//   [OUT_MD .. +MEM_LEN*256) new_mem_data
//   [OUT_IDX .. +MEM_LEN)    new_mem_idx (cast to float)
#define OUT_MEM_OFF 1LL
#define OUT_MD_OFF  (1LL + (long long)MEM_LEN * CODE_LEN)           // 8388609
#define OUT_IDX_OFF (OUT_MD_OFF + (long long)MEM_LEN * IN_DIM)      // 25165825

// Scratch (device globals — no allocation allowed)
__device__ float              g_colsum[IN_DIM];
__device__ float              g_colsq[IN_DIM];
__device__ float              g_enc[CODE_LEN];
__device__ int                g_minbits;
__device__ unsigned long long g_argmin;

// ---------------------------------------------------------------------------
// K0: reset accumulators (graph replays must start clean)
// ---------------------------------------------------------------------------
__global__ void k_init() {
    int t = threadIdx.x;
    g_colsum[t] = 0.0f;
    g_colsq[t]  = 0.0f;
    if (t == 0) {
        g_minbits = 0x7f800000;            // +inf bits
        g_argmin  = 0xFFFFFFFFFFFFFFFFULL; // max key
    }
}

// ---------------------------------------------------------------------------
// K1: column sum / sumsq over mem_data [MEM_LEN, IN_DIM] fused with the copy
//     to the output. blockDim == 256 == IN_DIM, grid-stride is a multiple of
//     256, so each thread's column index == tid for every iteration.
// ---------------------------------------------------------------------------
__global__ void k_stats(const float* __restrict__ md, float* __restrict__ out_md) {
    const long long N      = (long long)MEM_LEN * IN_DIM;
    const long long stride = (long long)gridDim.x * blockDim.x;
    int tid = threadIdx.x;
    float s = 0.0f, sq = 0.0f;
    for (long long i = (long long)blockIdx.x * blockDim.x + tid; i < N; i += stride) {
        float v = md[i];
        out_md[i] = v;
        s  += v;
        sq += v * v;
    }
    atomicAdd(&g_colsum[tid], s);
    atomicAdd(&g_colsq[tid],  sq);
}

// ---------------------------------------------------------------------------
// K2: finalize mean/std (ddof=1), normalize x, enc = new @ W.T + b
// ---------------------------------------------------------------------------
__global__ void k_enc(const float* __restrict__ x, const float* __restrict__ W,
                      const float* __restrict__ b) {
    __shared__ float s_new[IN_DIM];
    int t = threadIdx.x;
    float mean = g_colsum[t] * (1.0f / (float)MEM_LEN);
    float var  = (g_colsq[t] - (float)MEM_LEN * mean * mean) * (1.0f / (float)(MEM_LEN - 1));
    float sd   = sqrtf(fmaxf(var, 0.0f));
    float nv   = (sd == 0.0f) ? 0.0f : (x[t] - mean) / sd;
    s_new[t] = nv;
    __syncthreads();
    if (t < CODE_LEN) {
        float acc = b[t];
        const float* w = W + (long long)t * IN_DIM;
        #pragma unroll 8
        for (int i = 0; i < IN_DIM; i++) acc += s_new[i] * w[i];
        g_enc[t] = acc;
    }
}

// ---------------------------------------------------------------------------
// K3: warp-per-row L1 distance to g_enc over memory [MEM_LEN, CODE_LEN],
//     fused with the copy to the output. Lane l owns cols {l, l+32, l+64, l+96}
//     (coalesced loads and stores). Warp-shuffle row reduce, running min,
//     one atomicMin (int-bits of positive float) per warp.
// ---------------------------------------------------------------------------
__global__ void k_dist(const float* __restrict__ mem, float* __restrict__ out_mem) {
    int lane  = threadIdx.x & 31;
    int warp  = (blockIdx.x * blockDim.x + threadIdx.x) >> 5;
    int nwarp = (gridDim.x * blockDim.x) >> 5;
    float e0 = g_enc[lane], e1 = g_enc[lane + 32], e2 = g_enc[lane + 64], e3 = g_enc[lane + 96];
    float best = CUDART_INF_F;
    for (int row = warp; row < MEM_LEN; row += nwarp) {
        const float* r = mem + (long long)row * CODE_LEN;
        float*       o = out_mem + (long long)row * CODE_LEN;
        float v0 = r[lane], v1 = r[lane + 32], v2 = r[lane + 64], v3 = r[lane + 96];
        o[lane]      = v0;
        o[lane + 32] = v1;
        o[lane + 64] = v2;
        o[lane + 96] = v3;
        float d = fabsf(v0 - e0) + fabsf(v1 - e1) + fabsf(v2 - e2) + fabsf(v3 - e3);
        #pragma unroll
        for (int off = 16; off; off >>= 1) d += __shfl_xor_sync(0xFFFFFFFFu, d, off);
        best = fminf(best, d);
    }
    if (lane == 0) atomicMin(&g_minbits, __float_as_int(best));
}

// ---------------------------------------------------------------------------
// K4: argmin(mem_idx) with first-index tie-break + copy mem_idx -> out (as f32)
//     key = (val with sign bit flipped) << 32 | idx  -> unsigned 64-bit min.
// ---------------------------------------------------------------------------
__global__ void k_idx(const int* __restrict__ idx, float* __restrict__ out_idx) {
    unsigned g = blockIdx.x * blockDim.x + threadIdx.x;   // grid sized to MEM_LEN exactly
    int v = idx[g];
    out_idx[g] = (float)v;
    unsigned long long key =
        ((unsigned long long)(unsigned)(v ^ 0x80000000) << 32) | (unsigned long long)g;
    #pragma unroll
    for (int off = 16; off; off >>= 1) {
        unsigned long long o = __shfl_xor_sync(0xFFFFFFFFu, key, off);
        key = (o < key) ? o : key;
    }
    if ((threadIdx.x & 31) == 0) atomicMin(&g_argmin, key);
}

// ---------------------------------------------------------------------------
// K5: write loss; conditional scatter of enc / x / count at pos
// ---------------------------------------------------------------------------
__global__ void k_final(const float* __restrict__ x, const int* __restrict__ count,
                        float* __restrict__ out) {
    float loss = __int_as_float(g_minbits);
    int t = threadIdx.x;
    if (t == 0) out[0] = loss;
    if (loss <= 1.0f) {
        long long pos = (long long)(unsigned)(g_argmin & 0xFFFFFFFFULL);
        if (t < CODE_LEN) out[OUT_MEM_OFF + pos * CODE_LEN + t] = g_enc[t];
        out[OUT_MD_OFF + pos * IN_DIM + t] = x[t];   // t < 256 == IN_DIM
        if (t == 0) out[OUT_IDX_OFF + pos] = (float)count[0];
    }
}

// ---------------------------------------------------------------------------
extern "C" void kernel_launch(void* const* d_in, const int* in_sizes, int n_in,
                              void* d_out, int out_size) {
    const float* x        = (const float*)d_in[0];
    const float* memory   = (const float*)d_in[1];
    const float* mem_data = (const float*)d_in[2];
    const int*   mem_idx  = (const int*)d_in[3];
    const float* W        = (const float*)d_in[4];
    const float* b        = (const float*)d_in[5];
    const int*   count    = (const int*)d_in[6];
    float* out = (float*)d_out;

    k_init <<<1, 256>>>();
    k_stats<<<1024, 256>>>(mem_data, out + OUT_MD_OFF);
    k_idx  <<<MEM_LEN / 256, 256>>>(mem_idx, out + OUT_IDX_OFF);
    k_enc  <<<1, 256>>>(x, W, b);
    k_dist <<<1024, 256>>>(memory, out + OUT_MEM_OFF);
    k_final<<<1, 256>>>(x, count, out);
}

// round 2
// speedup vs baseline: 1.9816x; 1.9816x over previous
#include <cuda_runtime.h>
#include <math_constants.h>

#define IN_DIM   256
#define CODE_LEN 128
#define MEM_LEN  65536
// Output layout (all float32, flattened tuple):
//   [0] loss | [1..) new_memory | [OUT_MD..) new_mem_data | [OUT_IDX..) new_mem_idx
#define OUT_MEM_OFF 1LL
#define OUT_MD_OFF  (1LL + (long long)MEM_LEN * CODE_LEN)
#define OUT_IDX_OFF (OUT_MD_OFF + (long long)MEM_LEN * IN_DIM)

// Scratch (device globals; statically armed, re-armed at end of k_final)
__device__ float              g_colsum[IN_DIM];                 // zero-init
__device__ float              g_colsq[IN_DIM];                  // zero-init
__device__ __align__(16) float g_enc[CODE_LEN];
__device__ int                g_minbits = 0x7f800000;           // +inf bits
__device__ unsigned long long g_argmin  = 0xFFFFFFFFFFFFFFFFULL;

// ---------------------------------------------------------------------------
// K1: column sum/sumsq over mem_data [MEM_LEN, IN_DIM] (float4 loads) fused
//     with its output copy, PLUS the mem_idx copy + packed argmin.
//     stride*4 is a multiple of 256, so each thread's 4 columns are fixed:
//     col = (4*tid) & 255. Block-level smem reduction before global atomics.
// ---------------------------------------------------------------------------
__global__ void k_stats(const float4* __restrict__ md4, float* __restrict__ out_md,
                        const int* __restrict__ idx, float* __restrict__ out_idx) {
    const long long N4     = (long long)MEM_LEN * IN_DIM / 4;
    const long long stride = (long long)gridDim.x * blockDim.x;
    int tid = threadIdx.x;

    float s0 = 0, s1 = 0, s2 = 0, s3 = 0;
    float q0 = 0, q1 = 0, q2 = 0, q3 = 0;
    for (long long i = (long long)blockIdx.x * blockDim.x + tid; i < N4; i += stride) {
        float4 v = md4[i];
        float* o = out_md + i * 4;              // +1-float global offset -> scalar stores
        o[0] = v.x; o[1] = v.y; o[2] = v.z; o[3] = v.w;
        s0 += v.x; q0 += v.x * v.x;
        s1 += v.y; q1 += v.y * v.y;
        s2 += v.z; q2 += v.z * v.z;
        s3 += v.w; q3 += v.w * v.w;
    }

    // Block reduction: group g = tid>>6 (4 groups), each group covers all 256 cols once.
    __shared__ float sh_s[4][IN_DIM];
    __shared__ float sh_q[4][IN_DIM];
    int col = (4 * tid) & 255;
    int grp = tid >> 6;
    sh_s[grp][col + 0] = s0; sh_s[grp][col + 1] = s1; sh_s[grp][col + 2] = s2; sh_s[grp][col + 3] = s3;
    sh_q[grp][col + 0] = q0; sh_q[grp][col + 1] = q1; sh_q[grp][col + 2] = q2; sh_q[grp][col + 3] = q3;
    __syncthreads();
    float ts = sh_s[0][tid] + sh_s[1][tid] + sh_s[2][tid] + sh_s[3][tid];
    float tq = sh_q[0][tid] + sh_q[1][tid] + sh_q[2][tid] + sh_q[3][tid];
    atomicAdd(&g_colsum[tid], ts);
    atomicAdd(&g_colsq[tid],  tq);

    // mem_idx: copy + argmin (first-index tie-break via packed 64-bit key)
    unsigned g = blockIdx.x * blockDim.x + tid;
    if (g < MEM_LEN) {
        int v = idx[g];
        out_idx[g] = (float)v;
        unsigned long long key =
            ((unsigned long long)(unsigned)(v ^ 0x80000000) << 32) | (unsigned long long)g;
        #pragma unroll
        for (int off = 16; off; off >>= 1) {
            unsigned long long o = __shfl_xor_sync(0xFFFFFFFFu, key, off);
            key = (o < key) ? o : key;
        }
        if ((tid & 31) == 0) atomicMin(&g_argmin, key);
    }
}

// ---------------------------------------------------------------------------
// K2: enc = ((x-mean)/std) @ W.T + b, one output element per block (128 blocks).
// ---------------------------------------------------------------------------
__global__ void k_enc(const float* __restrict__ x, const float* __restrict__ W,
                      const float* __restrict__ b) {
    int row = blockIdx.x;
    int t   = threadIdx.x;
    float mean = g_colsum[t] * (1.0f / (float)MEM_LEN);
    float var  = (g_colsq[t] - (float)MEM_LEN * mean * mean) * (1.0f / (float)(MEM_LEN - 1));
    float sd   = sqrtf(fmaxf(var, 0.0f));
    float nv   = (sd == 0.0f) ? 0.0f : (x[t] - mean) / sd;
    float p    = nv * W[(long long)row * IN_DIM + t];
    #pragma unroll
    for (int off = 16; off; off >>= 1) p += __shfl_xor_sync(0xFFFFFFFFu, p, off);
    __shared__ float red[8];
    if ((t & 31) == 0) red[t >> 5] = p;
    __syncthreads();
    if (t == 0) {
        float a = b[row];
        #pragma unroll
        for (int i = 0; i < 8; i++) a += red[i];
        g_enc[row] = a;
    }
}

// ---------------------------------------------------------------------------
// K3: warp-per-row L1 distance over memory [MEM_LEN, CODE_LEN] fused with the
//     copy. One float4 per lane covers a whole 128-float row per warp.
// ---------------------------------------------------------------------------
__global__ void k_dist(const float4* __restrict__ mem4, float* __restrict__ out_mem) {
    int lane  = threadIdx.x & 31;
    int warp  = (blockIdx.x * blockDim.x + threadIdx.x) >> 5;
    int nwarp = (gridDim.x * blockDim.x) >> 5;
    float4 e = reinterpret_cast<const float4*>(g_enc)[lane];
    float best = CUDART_INF_F;
    for (int row = warp; row < MEM_LEN; row += nwarp) {
        float4 v = mem4[(long long)row * 32 + lane];
        float* o = out_mem + (long long)row * CODE_LEN + lane * 4;
        o[0] = v.x; o[1] = v.y; o[2] = v.z; o[3] = v.w;
        float d = fabsf(v.x - e.x) + fabsf(v.y - e.y) + fabsf(v.z - e.z) + fabsf(v.w - e.w);
        #pragma unroll
        for (int off = 16; off; off >>= 1) d += __shfl_xor_sync(0xFFFFFFFFu, d, off);
        best = fminf(best, d);
    }
    if (lane == 0) atomicMin(&g_minbits, __float_as_int(best));
}

// ---------------------------------------------------------------------------
// K4: loss write + conditional scatter, then re-arm all accumulators so the
//     next graph replay starts clean (no separate init launch).
// ---------------------------------------------------------------------------
__global__ void k_final(const float* __restrict__ x, const int* __restrict__ count,
                        float* __restrict__ out) {
    float loss = __int_as_float(g_minbits);
    long long pos = (long long)(unsigned)(g_argmin & 0xFFFFFFFFULL);
    int t = threadIdx.x;
    if (t == 0) out[0] = loss;
    if (loss <= 1.0f) {
        if (t < CODE_LEN) out[OUT_MEM_OFF + pos * CODE_LEN + t] = g_enc[t];
        out[OUT_MD_OFF + pos * IN_DIM + t] = x[t];
        if (t == 0) out[OUT_IDX_OFF + pos] = (float)count[0];
    }
    __syncthreads();   // everyone done reading the accumulators
    g_colsum[t] = 0.0f;
    g_colsq[t]  = 0.0f;
    if (t == 0) {
        g_minbits = 0x7f800000;
        g_argmin  = 0xFFFFFFFFFFFFFFFFULL;
    }
}

// ---------------------------------------------------------------------------
extern "C" void kernel_launch(void* const* d_in, const int* in_sizes, int n_in,
                              void* d_out, int out_size) {
    const float* x        = (const float*)d_in[0];
    const float* memory   = (const float*)d_in[1];
    const float* mem_data = (const float*)d_in[2];
    const int*   mem_idx  = (const int*)d_in[3];
    const float* W        = (const float*)d_in[4];
    const float* b        = (const float*)d_in[5];
    const int*   count    = (const int*)d_in[6];
    float* out = (float*)d_out;

    k_stats<<<1024, 256>>>((const float4*)mem_data, out + OUT_MD_OFF,
                           mem_idx, out + OUT_IDX_OFF);
    k_enc  <<<CODE_LEN, 256>>>(x, W, b);
    k_dist <<<1024, 256>>>((const float4*)memory, out + OUT_MEM_OFF);
    k_final<<<1, 256>>>(x, count, out);
}